// round 3
// baseline (speedup 1.0000x reference)
#include <cuda_runtime.h>
#include <cfloat>

// ---------------------------------------------------------------------------
// PillarMaxPooling: h = relu((x @ W) * bn_scale + bn_shift); segment_max -> M
// Two kernels only:
//   k1: counting-bucket scatter of point ids (int4-vectorized index read)
//   k2: warp-per-pillar gather (2 lanes per point -> coalesced-per-point LDG),
//       pair-packed f32x2 FMA mainloop, inline overflow handling, self-resets
//       d_count so no init kernel is needed (.bss starts zeroed).
// ---------------------------------------------------------------------------

#define CAP      64
#define MAXM     262144
#define OVFCAP   65536
#define BN_EPS   1e-3f
#define K2_THREADS 256
#define K2_WARPS   8

__device__ int   d_count[MAXM];                 // zero-initialized, k2 re-zeroes
__device__ int   d_bucket[(size_t)MAXM * CAP];
__device__ int   d_ovflist[OVFCAP];
__device__ int   d_ovfcnt;                      // zero-initialized, k2 re-zeroes

typedef unsigned long long u64;

__device__ __forceinline__ u64 pk2(float x, float y) {
    u64 r; asm("mov.b64 %0, {%1, %2};" : "=l"(r) : "f"(x), "f"(y)); return r;
}
__device__ __forceinline__ void upk2(u64 v, float& x, float& y) {
    asm("mov.b64 {%0, %1}, %2;" : "=f"(x), "=f"(y) : "l"(v));
}
__device__ __forceinline__ u64 fma2(u64 a, u64 b, u64 c) {
    u64 d; asm("fma.rn.f32x2 %0, %1, %2, %3;" : "=l"(d) : "l"(a), "l"(b), "l"(c)); return d;
}
__device__ __forceinline__ u64 mul2(u64 a, u64 b) {
    u64 d; asm("mul.rn.f32x2 %0, %1, %2;" : "=l"(d) : "l"(a), "l"(b)); return d;
}

__device__ __forceinline__ void put_point(const int* __restrict__ idx_unused, int i, int p) {
    int s = atomicAdd(&d_count[i], 1);
    if (s < CAP) {
        d_bucket[(size_t)i * CAP + s] = p;
    } else {
        int o = atomicAdd(&d_ovfcnt, 1);
        if (o < OVFCAP) d_ovflist[o] = p;
        else atomicSub(&d_ovfcnt, 1);   // keep counter consistent
    }
}

// K1: bucket the point ids per pillar.
__global__ void k1_scatter(const int* __restrict__ idx, int P) {
    int t  = blockIdx.x * blockDim.x + threadIdx.x;
    int p0 = t * 4;
    if (p0 + 3 < P) {
        int4 v = *reinterpret_cast<const int4*>(idx + p0);
        put_point(idx, v.x, p0);
        put_point(idx, v.y, p0 + 1);
        put_point(idx, v.z, p0 + 2);
        put_point(idx, v.w, p0 + 3);
    } else {
        for (int p = p0; p < P; p++) put_point(idx, idx[p], p);
    }
}

// K2: warp per pillar. Chunk of up to 16 points per iteration; lanes j and
// j+16 cooperatively load point j's 40B row (same cache line -> wavefronts
// scale with points, not lanes). SMEM pair-packed: word (p*20 + 2k + col)
// holds feature k of point 2p+col. Mainloop: f32x2 FMA, two points per chain.
__global__ void __launch_bounds__(K2_THREADS)
k2_compute(const float* __restrict__ gf, const float* __restrict__ W,
           const float* __restrict__ gamma, const float* __restrict__ beta,
           const float* __restrict__ mean,  const float* __restrict__ var,
           const int* __restrict__ idx, float* __restrict__ out, int M) {
    __shared__ __align__(16) float sm[K2_WARPS][160];   // 8 pairs x 20 words

    int lane = threadIdx.x & 31;
    int wloc = threadIdx.x >> 5;
    float* smw = sm[wloc];

    int gwarp = (blockIdx.x * K2_THREADS + threadIdx.x) >> 5;
    int nwarp = (gridDim.x * K2_THREADS) >> 5;

    // fold BN into weights (per-warp; inputs L1-hot after first warp)
    float sx = gamma[lane]      * rsqrtf(var[lane]      + BN_EPS);
    float sy = gamma[lane + 32] * rsqrtf(var[lane + 32] + BN_EPS);
    float bx = beta[lane]      - mean[lane]      * sx;
    float by = beta[lane + 32] - mean[lane + 32] * sy;

    u64 wl[10], wh[10];
#pragma unroll
    for (int k = 0; k < 10; k++) {
        float a = W[k * 64 + lane] * sx;
        float b = W[k * 64 + lane + 32] * sy;
        wl[k] = pk2(a, a);
        wh[k] = pk2(b, b);
    }

    int  j  = lane & 15;
    bool lo = lane < 16;

    for (int i = gwarp; i < M; i += nwarp) {
        int n  = d_count[i];
        int nc = n < CAP ? n : CAP;
        float mxl = -FLT_MAX, mxh = -FLT_MAX;

        for (int base = 0; base < nc; base += 16) {
            int m = nc - base; if (m > 16) m = 16;
            __syncwarp();
            if (j < m) {
                int pid = d_bucket[(size_t)i * CAP + base + j];
                const float2* fp2 = reinterpret_cast<const float2*>(gf + (size_t)pid * 10)
                                    + (lo ? 0 : 2);
                float2 A = fp2[0];
                float2 B = fp2[1];
                float* s = smw + (j >> 1) * 20 + (j & 1);
                int ks2 = lo ? 0 : 8;           // 2*k start
                s[ks2 + 0] = A.x;
                s[ks2 + 2] = A.y;
                s[ks2 + 4] = B.x;
                s[ks2 + 6] = B.y;
                if (!lo) {
                    float2 C = fp2[2];
                    s[16] = C.x;
                    s[18] = C.y;
                }
            }
            __syncwarp();

            int  pairs   = (m + 1) >> 1;
            bool odd     = (m & 1) != 0;
#pragma unroll 2
            for (int pr = 0; pr < pairs; pr++) {
                const ulonglong2* q = reinterpret_cast<const ulonglong2*>(smw + pr * 20);
                ulonglong2 q0 = q[0], q1 = q[1], q2 = q[2], q3 = q[3], q4 = q[4];
                u64 a = mul2(q0.x, wl[0]);
                u64 b = mul2(q0.x, wh[0]);
                a = fma2(q0.y, wl[1], a);  b = fma2(q0.y, wh[1], b);
                a = fma2(q1.x, wl[2], a);  b = fma2(q1.x, wh[2], b);
                a = fma2(q1.y, wl[3], a);  b = fma2(q1.y, wh[3], b);
                a = fma2(q2.x, wl[4], a);  b = fma2(q2.x, wh[4], b);
                a = fma2(q2.y, wl[5], a);  b = fma2(q2.y, wh[5], b);
                a = fma2(q3.x, wl[6], a);  b = fma2(q3.x, wh[6], b);
                a = fma2(q3.y, wl[7], a);  b = fma2(q3.y, wh[7], b);
                a = fma2(q4.x, wl[8], a);  b = fma2(q4.x, wh[8], b);
                a = fma2(q4.y, wl[9], a);  b = fma2(q4.y, wh[9], b);
                float de, dq, he, hq;
                upk2(a, de, dq);
                upk2(b, he, hq);
                if (odd && pr == pairs - 1) { dq = -FLT_MAX; hq = -FLT_MAX; }
                mxl = fmaxf(mxl, fmaxf(de, dq));
                mxh = fmaxf(mxh, fmaxf(he, hq));
            }
        }

        // inline overflow handling (statistically never taken)
        if (n > CAP) {
            int V = d_ovfcnt; if (V > OVFCAP) V = OVFCAP;
            int mine = 0;
            for (int e = 0; e < V; e++) {
                int pid = d_ovflist[e];
                if (idx[pid] == i) {
                    mine++;
                    u64 a = pk2(0.f, 0.f), b = a;
#pragma unroll
                    for (int k = 0; k < 10; k++) {
                        float f = gf[(size_t)pid * 10 + k];
                        u64 ff = pk2(f, f);
                        a = fma2(ff, wl[k], a);
                        b = fma2(ff, wh[k], b);
                    }
                    float dx, t0, hx, t1;
                    upk2(a, dx, t0); upk2(b, hx, t1);
                    mxl = fmaxf(mxl, dx);
                    mxh = fmaxf(mxh, hx);
                }
            }
            if (lane == 0 && mine) atomicSub(&d_ovfcnt, mine);
        }

        if (lane == 0) d_count[i] = 0;   // self-reset for next graph replay

        float r0 = 0.0f, r1 = 0.0f;
        if (n > 0) {
            r0 = fmaxf(mxl + bx, 0.0f);
            r1 = fmaxf(mxh + by, 0.0f);
        }
        out[(size_t)i * 64 + lane]      = r0;
        out[(size_t)i * 64 + lane + 32] = r1;
    }
}

extern "C" void kernel_launch(void* const* d_in, const int* in_sizes, int n_in,
                              void* d_out, int out_size) {
    const float* gf    = (const float*)d_in[0];
    const int*   idx   = (const int*)  d_in[1];
    const float* W     = (const float*)d_in[3];
    const float* gamma = (const float*)d_in[4];
    const float* beta  = (const float*)d_in[5];
    const float* mean  = (const float*)d_in[6];
    const float* var   = (const float*)d_in[7];
    float*       out   = (float*)d_out;

    int P = in_sizes[1];
    int M = out_size / 64;

    int t  = 256;
    int g1 = (P / 4 + t) / t;

    k1_scatter<<<g1, t>>>(idx, P);
    k2_compute<<<592, K2_THREADS>>>(gf, W, gamma, beta, mean, var, idx, out, M);
}